// round 2
// baseline (speedup 1.0000x reference)
#include <cuda_runtime.h>

// DifferentiableTTFSEncoder: first-fire one-hot over T=64 steps.
// out[b, t, n] = 1.0f at the first step t where mem = fma(mem, d, c*(1-d))
// crosses 1.0 (c = x[b,n]*sens[n]); 0.0 elsewhere. Exact fp32 recurrence
// replicated for bit-faithful threshold behavior.
//
// Store-bandwidth bound: 512 MB output. R2: 256-bit streaming stores
// (st.global.cs.v8.f32, Blackwell) to halve STG issue/wavefront count.

#define B_DIM 2048
#define N_DIM 1024
#define T_DIM 64
#define NG    (N_DIM / 8)   // 8-float groups per row = 128

__global__ void __launch_bounds__(128)
ttfs_kernel(const float* __restrict__ x,
            const float* __restrict__ sens,
            float* __restrict__ out)
{
    const int gid = blockIdx.x * blockDim.x + threadIdx.x;  // over B*N/8
    const int b  = gid >> 7;        // / NG
    const int ng = gid & (NG - 1);  // % NG

    // Load 8 x values and 8 sensitivity values (two float4 each, coalesced)
    const float4* x4 = reinterpret_cast<const float4*>(x);
    const float4* s4 = reinterpret_cast<const float4*>(sens);
    const float4 xa = x4[gid * 2 + 0];
    const float4 xb = x4[gid * 2 + 1];
    const float4 sa = s4[ng * 2 + 0];
    const float4 sb = s4[ng * 2 + 1];

    const float d   = 0.60653065971263342360f;  // exp(-0.5) rounded to fp32
    const float omd = 1.0f - d;

    float cc[8];
    cc[0] = xa.x * sa.x * omd;  cc[1] = xa.y * sa.y * omd;
    cc[2] = xa.z * sa.z * omd;  cc[3] = xa.w * sa.w * omd;
    cc[4] = xb.x * sb.x * omd;  cc[5] = xb.y * sb.y * omd;
    cc[6] = xb.z * sb.z * omd;  cc[7] = xb.w * sb.w * omd;

    float m[8];
    bool  f[8];
    #pragma unroll
    for (int i = 0; i < 8; ++i) { m[i] = 0.0f; f[i] = false; }

    // out[b, t, n] base, n = ng*8; per-t stride = N_DIM floats (4 KB)
    float* op = out + (size_t)b * (size_t)(T_DIM * N_DIM) + (size_t)(ng * 8);

    #pragma unroll
    for (int t = 0; t < T_DIM; ++t) {
        float v[8];
        #pragma unroll
        for (int i = 0; i < 8; ++i) {
            m[i] = fmaf(m[i], d, cc[i]);
            const bool s = (m[i] >= 1.0f);
            v[i] = (s && !f[i]) ? 1.0f : 0.0f;
            f[i] = f[i] || s;
        }
        // 256-bit streaming store (Blackwell STG.256, evict-first)
        asm volatile(
            "st.global.cs.v8.f32 [%0], {%1,%2,%3,%4,%5,%6,%7,%8};"
            :: "l"(op + (size_t)t * N_DIM),
               "f"(v[0]), "f"(v[1]), "f"(v[2]), "f"(v[3]),
               "f"(v[4]), "f"(v[5]), "f"(v[6]), "f"(v[7])
            : "memory");
    }
}

extern "C" void kernel_launch(void* const* d_in, const int* in_sizes, int n_in,
                              void* d_out, int out_size)
{
    const float* x    = (const float*)d_in[0];   // [2048, 1024] f32
    const float* sens = (const float*)d_in[1];   // [1024] f32
    float* out        = (float*)d_out;           // [2048, 64, 1024] f32

    const int total_threads = (B_DIM * N_DIM) / 8;  // 262144
    const int block = 128;
    const int grid  = total_threads / block;        // 2048

    ttfs_kernel<<<grid, block>>>(x, sens, out);
}